// round 2
// baseline (speedup 1.0000x reference)
#include <cuda_runtime.h>
#include <math_constants.h>

#define BB 64
#define DD 256
#define OO 1024
#define KK 1024

#define BLOCK_O 128
#define BLOCK_K 64
#define NT 256

// Scratch for ||e_k||^2 (allocation-free: __device__ global).
__device__ float g_e2[KK];

// ---------------------------------------------------------------------------
// Kernel 1: e2[k] = sum_d emb[d,k]^2.  Threads over k -> fully coalesced.
// ---------------------------------------------------------------------------
__global__ void e2_kernel(const float* __restrict__ emb) {
    int k = blockIdx.x * blockDim.x + threadIdx.x;
    float s = 0.f;
#pragma unroll 8
    for (int d = 0; d < DD; ++d) {
        float v = emb[d * KK + k];
        s = fmaf(v, v, s);
    }
    g_e2[k] = s;
}

// ---------------------------------------------------------------------------
// Kernel 2: fused GEMM + running argmin + gather.
// Block: one b, 128 o's. x-tile (256x128 f32) resident in smem,
// emb streamed in 256x64 tiles. Thread micro-tile: 8 o x 4 k.
// ---------------------------------------------------------------------------
extern __shared__ float smem[];

__global__ __launch_bounds__(NT, 1)
void vq_kernel(const float* __restrict__ x, const float* __restrict__ emb,
               float* __restrict__ quant, float* __restrict__ argout) {
    float* xs = smem;                    // [DD][BLOCK_O]  128 KB
    float* es = smem + DD * BLOCK_O;     // [DD][BLOCK_K]   64 KB
    __shared__ int ks[BLOCK_O];

    const int b  = blockIdx.y;
    const int o0 = blockIdx.x * BLOCK_O;
    const int tid = threadIdx.x;
    const int tx = tid & 15;   // k-group: 4 consecutive k
    const int ty = tid >> 4;   // o-group: 8 consecutive o

    // Load x tile: x[b, d, o0+o] -> xs[d*128 + o]. Consecutive tid = consecutive o
    // -> 512B coalesced rows.
    const float* xb = x + (size_t)b * DD * OO + o0;
    for (int idx = tid; idx < DD * BLOCK_O; idx += NT) {
        int d = idx >> 7;
        int o = idx & (BLOCK_O - 1);
        xs[idx] = xb[d * OO + o];
    }

    float bestv[8];
    int   bestk[8];
#pragma unroll
    for (int i = 0; i < 8; ++i) { bestv[i] = CUDART_INF_F; bestk[i] = 0; }

    for (int kt = 0; kt < KK; kt += BLOCK_K) {
        __syncthreads();   // prior compute done (and initial x load) before es overwrite
        for (int idx = tid; idx < DD * BLOCK_K; idx += NT) {
            int d = idx >> 6;
            int k = idx & (BLOCK_K - 1);
            es[idx] = emb[d * KK + kt + k];
        }
        __syncthreads();

        float acc[8][4];
#pragma unroll
        for (int i = 0; i < 8; ++i)
#pragma unroll
            for (int j = 0; j < 4; ++j) acc[i][j] = 0.f;

#pragma unroll 8
        for (int d = 0; d < DD; ++d) {
            const float4 a0 = reinterpret_cast<const float4*>(xs + d * BLOCK_O + ty * 8)[0];
            const float4 a1 = reinterpret_cast<const float4*>(xs + d * BLOCK_O + ty * 8)[1];
            const float4 bv = reinterpret_cast<const float4*>(es + d * BLOCK_K + tx * 4)[0];
            const float a[8] = {a0.x, a0.y, a0.z, a0.w, a1.x, a1.y, a1.z, a1.w};
            const float bq[4] = {bv.x, bv.y, bv.z, bv.w};
#pragma unroll
            for (int i = 0; i < 8; ++i)
#pragma unroll
                for (int j = 0; j < 4; ++j)
                    acc[i][j] = fmaf(a[i], bq[j], acc[i][j]);
        }

        // Running argmin update. Per-thread k strictly ascending across (kt, j)
        // so strict '<' keeps the first (lowest) index on ties, matching argmin.
#pragma unroll
        for (int j = 0; j < 4; ++j) {
            const int k = kt + tx * 4 + j;
            const float e2 = g_e2[k];
#pragma unroll
            for (int i = 0; i < 8; ++i) {
                float val = fmaf(-2.f, acc[i][j], e2);
                if (val < bestv[i]) { bestv[i] = val; bestk[i] = k; }
            }
        }
    }

    // Reduce across the 16 k-lanes (tx) sharing the same o rows.
    // tid = ty*16 + tx -> xor offsets <= 8 stay inside the 16-lane group.
#pragma unroll
    for (int i = 0; i < 8; ++i) {
        float v = bestv[i];
        int   kk = bestk[i];
#pragma unroll
        for (int off = 8; off >= 1; off >>= 1) {
            float ov = __shfl_xor_sync(0xFFFFFFFFu, v,  off);
            int   ok = __shfl_xor_sync(0xFFFFFFFFu, kk, off);
            if (ov < v || (ov == v && ok < kk)) { v = ov; kk = ok; }
        }
        if (tx == 0) {
            const int o = ty * 8 + i;
            ks[o] = kk;
            if (argout) argout[b * OO + o0 + o] = (float)kk;
        }
    }
    __syncthreads();

    // Gather quant[b,d,o] = emb[d, ks[o]]. Stores coalesced over o; loads hit
    // the L2-resident 1 MB codebook.
    if (quant) {
        float* qb = quant + (size_t)b * DD * OO + o0;
        for (int idx = tid; idx < DD * BLOCK_O; idx += NT) {
            int d = idx >> 7;
            int o = idx & (BLOCK_O - 1);
            qb[d * OO + o] = emb[d * KK + ks[o]];
        }
    }
}

// ---------------------------------------------------------------------------
extern "C" void kernel_launch(void* const* d_in, const int* in_sizes, int n_in,
                              void* d_out, int out_size) {
    const float* x   = (const float*)d_in[0];
    const float* emb = (const float*)d_in[1];
    float* out = (float*)d_out;

    const int QN = BB * DD * OO;   // quant elements
    const int AN = BB * OO;        // argmin elements

    float* quant  = nullptr;
    float* argout = nullptr;
    if (out_size >= QN) {
        quant = out;
        if (out_size >= QN + AN) argout = out + QN;
    } else if (out_size >= AN) {
        argout = out;   // argmin-only layout
    }

    const int smem_bytes = (DD * BLOCK_O + DD * BLOCK_K) * (int)sizeof(float); // 192 KB
    cudaFuncSetAttribute(vq_kernel, cudaFuncAttributeMaxDynamicSharedMemorySize, smem_bytes);

    e2_kernel<<<KK / 256, 256>>>(emb);

    dim3 grid(OO / BLOCK_O, BB);
    vq_kernel<<<grid, NT, smem_bytes>>>(x, emb, quant, argout);
}